// round 7
// baseline (speedup 1.0000x reference)
#include <cuda_runtime.h>
#include <cuda_bf16.h>
#include <math.h>
#include <cstdint>

#define BB 16
#define KK 256
#define ZZ 128
#define HH 128
#define M2P 384   // padded rows per batch in g_m2x: 256 m2z rows + 128 pair-max rows

// Scratch (allocation-free rule: __device__ globals)
__device__ float g_m1 [BB*KK*ZZ];    // m1z
__device__ float g_m2x[BB*M2P*ZZ];   // rows 0..255: m2z ; rows 256..383: pair-max
__device__ float g_m  [BB*KK*ZZ];    // relu(m1z + masked max)

// ===========================================================================
// mma.sync bf16 GEMM infrastructure (arch-stable: sm_80+, works at compute_103)
// ===========================================================================
#define LDH 136            // smem stride in halves (128 + 8 pad -> ldmatrix conflict-free)
#define OFF_BIAS 0         // 512 B
#define OFF_AHI  512                     // 64 x 136 halves = 17408 B
#define OFF_ALO  (OFF_AHI + 64*LDH*2)
#define OFF_BHI  (OFF_ALO + 64*LDH*2)    // 128 x 136 halves = 34816 B
#define OFF_BLO  (OFF_BHI + 128*LDH*2)
#define SMEM_BYTES (OFF_BLO + 128*LDH*2) // 104960 B

__device__ __forceinline__ uint32_t smem_to_u32(const void* p){
    uint32_t a;
    asm("{ .reg .u64 t; cvta.to.shared.u64 t, %1; cvt.u32.u64 %0, t; }"
        : "=r"(a) : "l"(p));
    return a;
}
__device__ __forceinline__ void ldsm4(uint32_t* r, uint32_t a){
    asm volatile("ldmatrix.sync.aligned.m8n8.x4.shared.b16 {%0,%1,%2,%3}, [%4];"
        : "=r"(r[0]), "=r"(r[1]), "=r"(r[2]), "=r"(r[3]) : "r"(a));
}
__device__ __forceinline__ void mma16816(float* c, const uint32_t* a, const uint32_t* b){
    asm volatile(
        "mma.sync.aligned.m16n8k16.row.col.f32.bf16.bf16.f32 "
        "{%0,%1,%2,%3}, {%4,%5,%6,%7}, {%8,%9}, {%0,%1,%2,%3};"
        : "+f"(c[0]), "+f"(c[1]), "+f"(c[2]), "+f"(c[3])
        : "r"(a[0]), "r"(a[1]), "r"(a[2]), "r"(a[3]), "r"(b[0]), "r"(b[1]));
}

// Stage rows x 128 f32 tile -> bf16 hi + lo, row-major [row][LDH] halves.
__device__ __forceinline__ void stage_rows(
    const float* __restrict__ src, int ldf, int rows,
    char* sm, int off_hi, int off_lo, int tid)
{
    for (int f = tid; f < rows * 32; f += 256){
        int r  = f >> 5;
        int c4 = f & 31;
        float4 v = *(const float4*)(src + (size_t)r * ldf + 4*c4);
        __nv_bfloat162 h0 = __floats2bfloat162_rn(v.x, v.y);
        __nv_bfloat162 h1 = __floats2bfloat162_rn(v.z, v.w);
        float l0 = v.x - __bfloat162float(h0.x);
        float l1 = v.y - __bfloat162float(h0.y);
        float l2 = v.z - __bfloat162float(h1.x);
        float l3 = v.w - __bfloat162float(h1.y);
        __nv_bfloat162 g0 = __floats2bfloat162_rn(l0, l1);
        __nv_bfloat162 g1 = __floats2bfloat162_rn(l2, l3);
        uint32_t byt = (uint32_t)(r * LDH + 4*c4) * 2u;
        uint2 hv; hv.x = *(uint32_t*)&h0; hv.y = *(uint32_t*)&h1;
        uint2 lv; lv.x = *(uint32_t*)&g0; lv.y = *(uint32_t*)&g1;
        *(uint2*)(sm + off_hi + byt) = hv;
        *(uint2*)(sm + off_lo + byt) = lv;
    }
}

// 8 k-steps over the staged K=128 chunk; warp tile 16 rows x 64 cols.
// acc[8][4] accumulates across calls (split terms: AhBh + AlBh + AhBl).
__device__ __forceinline__ void compute_chunk(
    uint32_t sb, int wr, int wc, int lane, float acc[8][4])
{
    #pragma unroll
    for (int ks = 0; ks < 8; ks++){
        const int k0 = ks * 16;
        uint32_t ah[4], al[4];
        {
            int arow = wr*16 + (lane & 15);
            int acol = k0 + 8*(lane >> 4);
            uint32_t aoff = (uint32_t)(arow * LDH + acol) * 2u;
            ldsm4(ah, sb + OFF_AHI + aoff);
            ldsm4(al, sb + OFF_ALO + aoff);
        }
        uint32_t bh[8][2], bl[8][2];
        #pragma unroll
        for (int p = 0; p < 4; p++){
            int brow = wc*64 + p*16 + (lane & 7) + ((lane >> 4) & 1)*8;
            int bcol = k0 + ((lane >> 3) & 1)*8;
            uint32_t boff = (uint32_t)(brow * LDH + bcol) * 2u;
            uint32_t r[4];
            ldsm4(r, sb + OFF_BHI + boff);
            bh[2*p  ][0] = r[0]; bh[2*p  ][1] = r[1];
            bh[2*p+1][0] = r[2]; bh[2*p+1][1] = r[3];
            ldsm4(r, sb + OFF_BLO + boff);
            bl[2*p  ][0] = r[0]; bl[2*p  ][1] = r[1];
            bl[2*p+1][0] = r[2]; bl[2*p+1][1] = r[3];
        }
        #pragma unroll
        for (int t = 0; t < 8; t++){
            mma16816(acc[t], ah, bh[t]);
            mma16816(acc[t], al, bh[t]);
            mma16816(acc[t], ah, bl[t]);
        }
    }
}

// ---------------------------------------------------------------------------
// KT1: m{1,2}z = z @ W{1,2}^T + b{1,2}.  grid (64 rowtiles, 2 mats), 256 thr.
// CTA: 64 rows x 128 cols, K=128 resident.
// ---------------------------------------------------------------------------
__global__ __launch_bounds__(256) void kt1_gemm(
    const float* __restrict__ z,
    const float* __restrict__ W1, const float* __restrict__ b1,
    const float* __restrict__ W2, const float* __restrict__ b2)
{
    extern __shared__ __align__(16) char sm[];
    const uint32_t sb = smem_to_u32(sm);
    const int tid  = threadIdx.x;
    const int wid  = tid >> 5, lane = tid & 31;
    const int wr   = wid >> 1, wc = wid & 1;
    const int row0 = blockIdx.x * 64;
    const int mat  = blockIdx.y;
    const float* __restrict__ W = mat ? W2 : W1;
    const float* __restrict__ b = mat ? b2 : b1;

    if (tid < 128) ((float*)(sm + OFF_BIAS))[tid] = __ldg(&b[tid]);
    stage_rows(z + (size_t)row0 * ZZ, ZZ, 64, sm, OFF_AHI, OFF_ALO, tid);
    stage_rows(W, ZZ, 128, sm, OFF_BHI, OFF_BLO, tid);
    __syncthreads();

    float acc[8][4];
    #pragma unroll
    for (int t = 0; t < 8; t++)
        #pragma unroll
        for (int c = 0; c < 4; c++) acc[t][c] = 0.f;

    compute_chunk(sb, wr, wc, lane, acc);

    const float* bias = (const float*)(sm + OFF_BIAS);
    #pragma unroll
    for (int t = 0; t < 8; t++){
        int gn   = wc*64 + t*8 + (lane & 3)*2;
        int rlo  = row0 + wr*16 + (lane >> 2);
        float bx = bias[gn], by = bias[gn+1];
        float2 v0 = make_float2(acc[t][0] + bx, acc[t][1] + by);
        float2 v1 = make_float2(acc[t][2] + bx, acc[t][3] + by);
        if (mat == 0){
            *(float2*)(g_m1 + (size_t)rlo * ZZ + gn)       = v0;
            *(float2*)(g_m1 + (size_t)(rlo + 8) * ZZ + gn) = v1;
        } else {
            int b0 = rlo >> 8,       i0 = rlo & 255;
            int b8 = (rlo + 8) >> 8, i8 = (rlo + 8) & 255;
            *(float2*)(g_m2x + ((size_t)b0 * M2P + i0) * ZZ + gn) = v0;
            *(float2*)(g_m2x + ((size_t)b8 * M2P + i8) * ZZ + gn) = v1;
        }
    }
}

// ---------------------------------------------------------------------------
// K2a: pair-max rows: g_m2x[b][256+jp] = max(g_m2x[b][2jp], g_m2x[b][2jp+1])
// ---------------------------------------------------------------------------
__global__ __launch_bounds__(256) void k2a_pairmax()
{
    int t  = blockIdx.x * 256 + threadIdx.x;     // 0..65535
    int b  = t >> 12;
    int r  = t & 4095;
    int jp = r >> 5;
    int q  = r & 31;
    const float4* rows = (const float4*)g_m2x;
    float4 a = rows[((size_t)b * M2P + 2*jp    ) * 32 + q];
    float4 c = rows[((size_t)b * M2P + 2*jp + 1) * 32 + q];
    float4 m;
    m.x = fmaxf(a.x, c.x); m.y = fmaxf(a.y, c.y);
    m.z = fmaxf(a.z, c.z); m.w = fmaxf(a.w, c.w);
    ((float4*)g_m2x)[((size_t)b * M2P + 256 + jp) * 32 + q] = m;
}

// ---------------------------------------------------------------------------
// K2: m[b,i,:] = relu(m1z[b,i,:] + max_{j: P[b,j,i]!=0} m2z[b,j,:])
// Warp = one i. Pair-collapsed neighbor list, unroll-8 MLP loop.
// ---------------------------------------------------------------------------
__global__ __launch_bounds__(512) void k2_maxmsg(const int* __restrict__ P)
{
    __shared__ int PsT[16][257];
    __shared__ unsigned short lists[16][128];
    const int b   = blockIdx.y;
    const int i0  = blockIdx.x * 16;
    const int tid = threadIdx.x;

    for (int idx = tid; idx < KK * 16; idx += 512) {
        int j = idx >> 4, il = idx & 15;
        PsT[il][j] = P[(b * KK + j) * KK + i0 + il];
    }
    __syncthreads();

    const int w    = tid >> 5;
    const int lane = tid & 31;

    int cnt = 0;
    #pragma unroll
    for (int jb = 0; jb < 128; jb += 32) {
        int jp = jb + lane;
        int f0 = PsT[w][2*jp];
        int f1 = PsT[w][2*jp + 1];
        int present = (f0 | f1) != 0;
        int idx = (f0 && f1) ? (256 + jp) : (f0 ? 2*jp : 2*jp + 1);
        unsigned bal = __ballot_sync(0xffffffffu, present);
        if (present) {
            int pos = cnt + __popc(bal & ((1u << lane) - 1u));
            lists[w][pos] = (unsigned short)idx;
        }
        cnt += __popc(bal);
    }
    __syncwarp();

    const float* base = g_m2x + (size_t)b * M2P * ZZ + lane * 4;
    float4 acc = make_float4(-INFINITY, -INFINITY, -INFINITY, -INFINITY);

    int e = 0;
    for (; e + 8 <= cnt; e += 8) {
        ushort4 ja = *(const ushort4*)&lists[w][e];
        ushort4 jb = *(const ushort4*)&lists[w][e + 4];
        float4 v0 = *(const float4*)(base + (int)ja.x * ZZ);
        float4 v1 = *(const float4*)(base + (int)ja.y * ZZ);
        float4 v2 = *(const float4*)(base + (int)ja.z * ZZ);
        float4 v3 = *(const float4*)(base + (int)ja.w * ZZ);
        float4 v4 = *(const float4*)(base + (int)jb.x * ZZ);
        float4 v5 = *(const float4*)(base + (int)jb.y * ZZ);
        float4 v6 = *(const float4*)(base + (int)jb.z * ZZ);
        float4 v7 = *(const float4*)(base + (int)jb.w * ZZ);
        acc.x = fmaxf(acc.x, fmaxf(fmaxf(fmaxf(v0.x,v1.x),fmaxf(v2.x,v3.x)),
                                   fmaxf(fmaxf(v4.x,v5.x),fmaxf(v6.x,v7.x))));
        acc.y = fmaxf(acc.y, fmaxf(fmaxf(fmaxf(v0.y,v1.y),fmaxf(v2.y,v3.y)),
                                   fmaxf(fmaxf(v4.y,v5.y),fmaxf(v6.y,v7.y))));
        acc.z = fmaxf(acc.z, fmaxf(fmaxf(fmaxf(v0.z,v1.z),fmaxf(v2.z,v3.z)),
                                   fmaxf(fmaxf(v4.z,v5.z),fmaxf(v6.z,v7.z))));
        acc.w = fmaxf(acc.w, fmaxf(fmaxf(fmaxf(v0.w,v1.w),fmaxf(v2.w,v3.w)),
                                   fmaxf(fmaxf(v4.w,v5.w),fmaxf(v6.w,v7.w))));
    }
    for (; e + 4 <= cnt; e += 4) {
        ushort4 jj = *(const ushort4*)&lists[w][e];
        float4 v0 = *(const float4*)(base + (int)jj.x * ZZ);
        float4 v1 = *(const float4*)(base + (int)jj.y * ZZ);
        float4 v2 = *(const float4*)(base + (int)jj.z * ZZ);
        float4 v3 = *(const float4*)(base + (int)jj.w * ZZ);
        acc.x = fmaxf(fmaxf(fmaxf(acc.x, v0.x), fmaxf(v1.x, v2.x)), v3.x);
        acc.y = fmaxf(fmaxf(fmaxf(acc.y, v0.y), fmaxf(v1.y, v2.y)), v3.y);
        acc.z = fmaxf(fmaxf(fmaxf(acc.z, v0.z), fmaxf(v1.z, v2.z)), v3.z);
        acc.w = fmaxf(fmaxf(fmaxf(acc.w, v0.w), fmaxf(v1.w, v2.w)), v3.w);
    }
    for (; e < cnt; e++) {
        int j = lists[w][e];
        float4 v = *(const float4*)(base + j * ZZ);
        acc.x = fmaxf(acc.x, v.x);
        acc.y = fmaxf(acc.y, v.y);
        acc.z = fmaxf(acc.z, v.z);
        acc.w = fmaxf(acc.w, v.w);
    }

    const size_t off = ((size_t)b * KK + i0 + w) * ZZ + lane * 4;
    float4 m1 = *(const float4*)(g_m1 + off);
    float4 m;
    m.x = fmaxf(m1.x + acc.x, 0.f);
    m.y = fmaxf(m1.y + acc.y, 0.f);
    m.z = fmaxf(m1.z + acc.z, 0.f);
    m.w = fmaxf(m1.w + acc.w, 0.f);
    *(float4*)(g_m + off) = m;
}

// ---------------------------------------------------------------------------
// KT3: out = relu([z|m] @ Wu^T + bu).  grid 64 rowtiles, 256 thr.
// Two K-chunks (z with Wu[:,0:128], m with Wu[:,128:256]) accumulate in regs.
// ---------------------------------------------------------------------------
__global__ __launch_bounds__(256) void kt3_gemm(
    const float* __restrict__ z,
    const float* __restrict__ Wu, const float* __restrict__ bu,
    float* __restrict__ out)
{
    extern __shared__ __align__(16) char sm[];
    const uint32_t sb = smem_to_u32(sm);
    const int tid  = threadIdx.x;
    const int wid  = tid >> 5, lane = tid & 31;
    const int wr   = wid >> 1, wc = wid & 1;
    const int row0 = blockIdx.x * 64;

    if (tid < 128) ((float*)(sm + OFF_BIAS))[tid] = __ldg(&bu[tid]);

    float acc[8][4];
    #pragma unroll
    for (int t = 0; t < 8; t++)
        #pragma unroll
        for (int c = 0; c < 4; c++) acc[t][c] = 0.f;

    // chunk 0: A = z rows, B = Wu[:, 0:128]
    stage_rows(z + (size_t)row0 * ZZ, ZZ, 64, sm, OFF_AHI, OFF_ALO, tid);
    stage_rows(Wu, 2 * ZZ, 128, sm, OFF_BHI, OFF_BLO, tid);
    __syncthreads();
    compute_chunk(sb, wr, wc, lane, acc);
    __syncthreads();

    // chunk 1: A = g_m rows, B = Wu[:, 128:256]
    stage_rows(g_m + (size_t)row0 * ZZ, ZZ, 64, sm, OFF_AHI, OFF_ALO, tid);
    stage_rows(Wu + ZZ, 2 * ZZ, 128, sm, OFF_BHI, OFF_BLO, tid);
    __syncthreads();
    compute_chunk(sb, wr, wc, lane, acc);

    const float* bias = (const float*)(sm + OFF_BIAS);
    #pragma unroll
    for (int t = 0; t < 8; t++){
        int gn  = wc*64 + t*8 + (lane & 3)*2;
        int rlo = row0 + wr*16 + (lane >> 2);
        float bx = bias[gn], by = bias[gn+1];
        float2 v0 = make_float2(fmaxf(acc[t][0] + bx, 0.f), fmaxf(acc[t][1] + by, 0.f));
        float2 v1 = make_float2(fmaxf(acc[t][2] + bx, 0.f), fmaxf(acc[t][3] + by, 0.f));
        *(float2*)(out + (size_t)rlo * HH + gn)       = v0;
        *(float2*)(out + (size_t)(rlo + 8) * HH + gn) = v1;
    }
}

// ---------------------------------------------------------------------------
extern "C" void kernel_launch(void* const* d_in, const int* in_sizes, int n_in,
                              void* d_out, int out_size)
{
    const float* z  = (const float*)d_in[0];
    const int*   P  = (const int*)  d_in[1];
    const float* W1 = (const float*)d_in[2];
    const float* b1 = (const float*)d_in[3];
    const float* W2 = (const float*)d_in[4];
    const float* b2 = (const float*)d_in[5];
    const float* Wu = (const float*)d_in[6];
    const float* bu = (const float*)d_in[7];
    float* out = (float*)d_out;

    static bool attr_done = false;
    if (!attr_done){
        cudaFuncSetAttribute(kt1_gemm, cudaFuncAttributeMaxDynamicSharedMemorySize, SMEM_BYTES);
        cudaFuncSetAttribute(kt3_gemm, cudaFuncAttributeMaxDynamicSharedMemorySize, SMEM_BYTES);
        attr_done = true;
    }

    kt1_gemm<<<dim3(BB * KK / 64, 2), 256, SMEM_BYTES>>>(z, W1, b1, W2, b2);
    k2a_pairmax<<<256, 256>>>();
    k2_maxmsg<<<dim3(KK / 16, BB), 512>>>(P);
    kt3_gemm<<<BB * KK / 64, 256, SMEM_BYTES>>>(z, Wu, bu, out);
}

// round 8
// speedup vs baseline: 1.1079x; 1.1079x over previous
#include <cuda_runtime.h>
#include <cuda_bf16.h>
#include <math.h>
#include <cstdint>

#define BB 16
#define KK 256
#define ZZ 128
#define HH 128
#define M2P 384   // padded rows per batch in g_m2x: 256 m2z rows + 128 pair-max rows

// Scratch (allocation-free rule: __device__ globals)
__device__ float g_m1 [BB*KK*ZZ];    // m1z
__device__ float g_m2x[BB*M2P*ZZ];   // rows 0..255: m2z ; rows 256..383: pair-max
__device__ float g_m  [BB*KK*ZZ];    // relu(m1z + masked max)
__device__ float g_p  [2*BB*KK*HH];  // kt3 split-K partials

// ===========================================================================
// mma.sync bf16 GEMM infrastructure (arch-stable: sm_80+, works at compute_103)
// Tile: 32 rows x 128 cols, K=128 chunk resident as bf16 hi+lo.
// ===========================================================================
#define LDH 136            // smem stride in halves (128 + 8 pad -> ldmatrix conflict-free)
#define OFF_BIAS 0                        // 512 B
#define OFF_AHI  512                      // 32 x 136 halves = 8704 B
#define OFF_ALO  (OFF_AHI + 32*LDH*2)
#define OFF_BHI  (OFF_ALO + 32*LDH*2)     // 128 x 136 halves = 34816 B
#define OFF_BLO  (OFF_BHI + 128*LDH*2)
#define SMEM_BYTES (OFF_BLO + 128*LDH*2)  // 87552 B -> 2 CTAs/SM

__device__ __forceinline__ uint32_t smem_to_u32(const void* p){
    uint32_t a;
    asm("{ .reg .u64 t; cvta.to.shared.u64 t, %1; cvt.u32.u64 %0, t; }"
        : "=r"(a) : "l"(p));
    return a;
}
__device__ __forceinline__ void ldsm4(uint32_t* r, uint32_t a){
    asm volatile("ldmatrix.sync.aligned.m8n8.x4.shared.b16 {%0,%1,%2,%3}, [%4];"
        : "=r"(r[0]), "=r"(r[1]), "=r"(r[2]), "=r"(r[3]) : "r"(a));
}
__device__ __forceinline__ void mma16816(float* c, const uint32_t* a, const uint32_t* b){
    asm volatile(
        "mma.sync.aligned.m16n8k16.row.col.f32.bf16.bf16.f32 "
        "{%0,%1,%2,%3}, {%4,%5,%6,%7}, {%8,%9}, {%0,%1,%2,%3};"
        : "+f"(c[0]), "+f"(c[1]), "+f"(c[2]), "+f"(c[3])
        : "r"(a[0]), "r"(a[1]), "r"(a[2]), "r"(a[3]), "r"(b[0]), "r"(b[1]));
}

// Stage rows x 128 f32 tile -> bf16 hi + lo, row-major [row][LDH] halves.
__device__ __forceinline__ void stage_rows(
    const float* __restrict__ src, int ldf, int rows,
    char* sm, int off_hi, int off_lo, int tid)
{
    for (int f = tid; f < rows * 32; f += 128){
        int r  = f >> 5;
        int c4 = f & 31;
        float4 v = *(const float4*)(src + (size_t)r * ldf + 4*c4);
        __nv_bfloat162 h0 = __floats2bfloat162_rn(v.x, v.y);
        __nv_bfloat162 h1 = __floats2bfloat162_rn(v.z, v.w);
        float l0 = v.x - __bfloat162float(h0.x);
        float l1 = v.y - __bfloat162float(h0.y);
        float l2 = v.z - __bfloat162float(h1.x);
        float l3 = v.w - __bfloat162float(h1.y);
        __nv_bfloat162 g0 = __floats2bfloat162_rn(l0, l1);
        __nv_bfloat162 g1 = __floats2bfloat162_rn(l2, l3);
        uint32_t byt = (uint32_t)(r * LDH + 4*c4) * 2u;
        uint2 hv; hv.x = *(uint32_t*)&h0; hv.y = *(uint32_t*)&h1;
        uint2 lv; lv.x = *(uint32_t*)&g0; lv.y = *(uint32_t*)&g1;
        *(uint2*)(sm + off_hi + byt) = hv;
        *(uint2*)(sm + off_lo + byt) = lv;
    }
}

// 8 k-steps over the staged K=128 chunk; warp tile 16 rows x 64 cols.
// 4 warps: wr = wid>>1 (0..1), wc = wid&1 (0..1).
// acc[8][4] accumulates split terms: AhBh + AlBh + AhBl.
__device__ __forceinline__ void compute_chunk(
    uint32_t sb, int wr, int wc, int lane, float acc[8][4])
{
    #pragma unroll
    for (int ks = 0; ks < 8; ks++){
        const int k0 = ks * 16;
        uint32_t ah[4], al[4];
        {
            int arow = wr*16 + (lane & 15);
            int acol = k0 + 8*(lane >> 4);
            uint32_t aoff = (uint32_t)(arow * LDH + acol) * 2u;
            ldsm4(ah, sb + OFF_AHI + aoff);
            ldsm4(al, sb + OFF_ALO + aoff);
        }
        uint32_t bh[8][2], bl[8][2];
        #pragma unroll
        for (int p = 0; p < 4; p++){
            int brow = wc*64 + p*16 + (lane & 7) + ((lane >> 4) & 1)*8;
            int bcol = k0 + ((lane >> 3) & 1)*8;
            uint32_t boff = (uint32_t)(brow * LDH + bcol) * 2u;
            uint32_t r[4];
            ldsm4(r, sb + OFF_BHI + boff);
            bh[2*p  ][0] = r[0]; bh[2*p  ][1] = r[1];
            bh[2*p+1][0] = r[2]; bh[2*p+1][1] = r[3];
            ldsm4(r, sb + OFF_BLO + boff);
            bl[2*p  ][0] = r[0]; bl[2*p  ][1] = r[1];
            bl[2*p+1][0] = r[2]; bl[2*p+1][1] = r[3];
        }
        #pragma unroll
        for (int t = 0; t < 8; t++){
            mma16816(acc[t], ah, bh[t]);
            mma16816(acc[t], al, bh[t]);
            mma16816(acc[t], ah, bl[t]);
        }
    }
}

// ---------------------------------------------------------------------------
// KT1: m{1,2}z = z @ W{1,2}^T + b{1,2}.  grid (128 rowtiles, 2 mats), 128 thr.
// ---------------------------------------------------------------------------
__global__ __launch_bounds__(128) void kt1_gemm(
    const float* __restrict__ z,
    const float* __restrict__ W1, const float* __restrict__ b1,
    const float* __restrict__ W2, const float* __restrict__ b2)
{
    extern __shared__ __align__(16) char sm[];
    const uint32_t sb = smem_to_u32(sm);
    const int tid  = threadIdx.x;
    const int wid  = tid >> 5, lane = tid & 31;
    const int wr   = wid >> 1, wc = wid & 1;
    const int row0 = blockIdx.x * 32;
    const int mat  = blockIdx.y;
    const float* __restrict__ W = mat ? W2 : W1;
    const float* __restrict__ b = mat ? b2 : b1;

    ((float*)(sm + OFF_BIAS))[tid] = __ldg(&b[tid]);
    stage_rows(z + (size_t)row0 * ZZ, ZZ, 32, sm, OFF_AHI, OFF_ALO, tid);
    stage_rows(W, ZZ, 128, sm, OFF_BHI, OFF_BLO, tid);
    __syncthreads();

    float acc[8][4];
    #pragma unroll
    for (int t = 0; t < 8; t++)
        #pragma unroll
        for (int c = 0; c < 4; c++) acc[t][c] = 0.f;

    compute_chunk(sb, wr, wc, lane, acc);

    const float* bias = (const float*)(sm + OFF_BIAS);
    #pragma unroll
    for (int t = 0; t < 8; t++){
        int gn   = wc*64 + t*8 + (lane & 3)*2;
        int rlo  = row0 + wr*16 + (lane >> 2);
        float bx = bias[gn], by = bias[gn+1];
        float2 v0 = make_float2(acc[t][0] + bx, acc[t][1] + by);
        float2 v1 = make_float2(acc[t][2] + bx, acc[t][3] + by);
        if (mat == 0){
            *(float2*)(g_m1 + (size_t)rlo * ZZ + gn)       = v0;
            *(float2*)(g_m1 + (size_t)(rlo + 8) * ZZ + gn) = v1;
        } else {
            int b0 = rlo >> 8,       i0 = rlo & 255;
            int b8 = (rlo + 8) >> 8, i8 = (rlo + 8) & 255;
            *(float2*)(g_m2x + ((size_t)b0 * M2P + i0) * ZZ + gn) = v0;
            *(float2*)(g_m2x + ((size_t)b8 * M2P + i8) * ZZ + gn) = v1;
        }
    }
}

// ---------------------------------------------------------------------------
// K2a: pair-max rows: g_m2x[b][256+jp] = max(g_m2x[b][2jp], g_m2x[b][2jp+1])
// ---------------------------------------------------------------------------
__global__ __launch_bounds__(256) void k2a_pairmax()
{
    int t  = blockIdx.x * 256 + threadIdx.x;     // 0..65535
    int b  = t >> 12;
    int r  = t & 4095;
    int jp = r >> 5;
    int q  = r & 31;
    const float4* rows = (const float4*)g_m2x;
    float4 a = rows[((size_t)b * M2P + 2*jp    ) * 32 + q];
    float4 c = rows[((size_t)b * M2P + 2*jp + 1) * 32 + q];
    float4 m;
    m.x = fmaxf(a.x, c.x); m.y = fmaxf(a.y, c.y);
    m.z = fmaxf(a.z, c.z); m.w = fmaxf(a.w, c.w);
    ((float4*)g_m2x)[((size_t)b * M2P + 256 + jp) * 32 + q] = m;
}

// ---------------------------------------------------------------------------
// K2: m[b,i,:] = relu(m1z[b,i,:] + max_{j: P[b,j,i]!=0} m2z[b,j,:])
// Warp = one i. Pair-collapsed neighbor list, unroll-8 MLP loop.
// ---------------------------------------------------------------------------
__global__ __launch_bounds__(512) void k2_maxmsg(const int* __restrict__ P)
{
    __shared__ int PsT[16][257];
    __shared__ unsigned short lists[16][128];
    const int b   = blockIdx.y;
    const int i0  = blockIdx.x * 16;
    const int tid = threadIdx.x;

    for (int idx = tid; idx < KK * 16; idx += 512) {
        int j = idx >> 4, il = idx & 15;
        PsT[il][j] = P[(b * KK + j) * KK + i0 + il];
    }
    __syncthreads();

    const int w    = tid >> 5;
    const int lane = tid & 31;

    int cnt = 0;
    #pragma unroll
    for (int jb = 0; jb < 128; jb += 32) {
        int jp = jb + lane;
        int f0 = PsT[w][2*jp];
        int f1 = PsT[w][2*jp + 1];
        int present = (f0 | f1) != 0;
        int idx = (f0 && f1) ? (256 + jp) : (f0 ? 2*jp : 2*jp + 1);
        unsigned bal = __ballot_sync(0xffffffffu, present);
        if (present) {
            int pos = cnt + __popc(bal & ((1u << lane) - 1u));
            lists[w][pos] = (unsigned short)idx;
        }
        cnt += __popc(bal);
    }
    __syncwarp();

    const float* base = g_m2x + (size_t)b * M2P * ZZ + lane * 4;
    float4 acc = make_float4(-INFINITY, -INFINITY, -INFINITY, -INFINITY);

    int e = 0;
    for (; e + 8 <= cnt; e += 8) {
        ushort4 ja = *(const ushort4*)&lists[w][e];
        ushort4 jb = *(const ushort4*)&lists[w][e + 4];
        float4 v0 = *(const float4*)(base + (int)ja.x * ZZ);
        float4 v1 = *(const float4*)(base + (int)ja.y * ZZ);
        float4 v2 = *(const float4*)(base + (int)ja.z * ZZ);
        float4 v3 = *(const float4*)(base + (int)ja.w * ZZ);
        float4 v4 = *(const float4*)(base + (int)jb.x * ZZ);
        float4 v5 = *(const float4*)(base + (int)jb.y * ZZ);
        float4 v6 = *(const float4*)(base + (int)jb.z * ZZ);
        float4 v7 = *(const float4*)(base + (int)jb.w * ZZ);
        acc.x = fmaxf(acc.x, fmaxf(fmaxf(fmaxf(v0.x,v1.x),fmaxf(v2.x,v3.x)),
                                   fmaxf(fmaxf(v4.x,v5.x),fmaxf(v6.x,v7.x))));
        acc.y = fmaxf(acc.y, fmaxf(fmaxf(fmaxf(v0.y,v1.y),fmaxf(v2.y,v3.y)),
                                   fmaxf(fmaxf(v4.y,v5.y),fmaxf(v6.y,v7.y))));
        acc.z = fmaxf(acc.z, fmaxf(fmaxf(fmaxf(v0.z,v1.z),fmaxf(v2.z,v3.z)),
                                   fmaxf(fmaxf(v4.z,v5.z),fmaxf(v6.z,v7.z))));
        acc.w = fmaxf(acc.w, fmaxf(fmaxf(fmaxf(v0.w,v1.w),fmaxf(v2.w,v3.w)),
                                   fmaxf(fmaxf(v4.w,v5.w),fmaxf(v6.w,v7.w))));
    }
    for (; e + 4 <= cnt; e += 4) {
        ushort4 jj = *(const ushort4*)&lists[w][e];
        float4 v0 = *(const float4*)(base + (int)jj.x * ZZ);
        float4 v1 = *(const float4*)(base + (int)jj.y * ZZ);
        float4 v2 = *(const float4*)(base + (int)jj.z * ZZ);
        float4 v3 = *(const float4*)(base + (int)jj.w * ZZ);
        acc.x = fmaxf(fmaxf(fmaxf(acc.x, v0.x), fmaxf(v1.x, v2.x)), v3.x);
        acc.y = fmaxf(fmaxf(fmaxf(acc.y, v0.y), fmaxf(v1.y, v2.y)), v3.y);
        acc.z = fmaxf(fmaxf(fmaxf(acc.z, v0.z), fmaxf(v1.z, v2.z)), v3.z);
        acc.w = fmaxf(fmaxf(fmaxf(acc.w, v0.w), fmaxf(v1.w, v2.w)), v3.w);
    }
    for (; e < cnt; e++) {
        int j = lists[w][e];
        float4 v = *(const float4*)(base + j * ZZ);
        acc.x = fmaxf(acc.x, v.x);
        acc.y = fmaxf(acc.y, v.y);
        acc.z = fmaxf(acc.z, v.z);
        acc.w = fmaxf(acc.w, v.w);
    }

    const size_t off = ((size_t)b * KK + i0 + w) * ZZ + lane * 4;
    float4 m1 = *(const float4*)(g_m1 + off);
    float4 m;
    m.x = fmaxf(m1.x + acc.x, 0.f);
    m.y = fmaxf(m1.y + acc.y, 0.f);
    m.z = fmaxf(m1.z + acc.z, 0.f);
    m.w = fmaxf(m1.w + acc.w, 0.f);
    *(float4*)(g_m + off) = m;
}

// ---------------------------------------------------------------------------
// KT3: split-K partials. ksplit 0: z @ WuL^T ; ksplit 1: m @ WuR^T.
// grid (128 rowtiles, 2 ksplit), 128 thr. Each CTA does ONE K=128 chunk.
// ---------------------------------------------------------------------------
__global__ __launch_bounds__(128) void kt3_gemm(
    const float* __restrict__ z,
    const float* __restrict__ Wu)
{
    extern __shared__ __align__(16) char sm[];
    const uint32_t sb = smem_to_u32(sm);
    const int tid  = threadIdx.x;
    const int wid  = tid >> 5, lane = tid & 31;
    const int wr   = wid >> 1, wc = wid & 1;
    const int row0 = blockIdx.x * 32;
    const int ksplit = blockIdx.y;
    const float* __restrict__ src =
        ksplit ? (g_m + (size_t)row0 * ZZ) : (z + (size_t)row0 * ZZ);

    stage_rows(src, ZZ, 32, sm, OFF_AHI, OFF_ALO, tid);
    stage_rows(Wu + ksplit * ZZ, 2 * ZZ, 128, sm, OFF_BHI, OFF_BLO, tid);
    __syncthreads();

    float acc[8][4];
    #pragma unroll
    for (int t = 0; t < 8; t++)
        #pragma unroll
        for (int c = 0; c < 4; c++) acc[t][c] = 0.f;

    compute_chunk(sb, wr, wc, lane, acc);

    float* dst = g_p + (size_t)ksplit * (BB * KK * HH);
    #pragma unroll
    for (int t = 0; t < 8; t++){
        int gn  = wc*64 + t*8 + (lane & 3)*2;
        int rlo = row0 + wr*16 + (lane >> 2);
        *(float2*)(dst + (size_t)rlo * HH + gn)       = make_float2(acc[t][0], acc[t][1]);
        *(float2*)(dst + (size_t)(rlo + 8) * HH + gn) = make_float2(acc[t][2], acc[t][3]);
    }
}

// ---------------------------------------------------------------------------
// KT3 epilogue: out = relu(p0 + p1 + bu), float4-vectorized.
// ---------------------------------------------------------------------------
__global__ __launch_bounds__(256) void k3_epi(
    const float* __restrict__ bu, float* __restrict__ out)
{
    int t = blockIdx.x * 256 + threadIdx.x;      // 0..131071 (float4 lanes)
    const float4* p4 = (const float4*)g_p;
    float4 a = p4[t];
    float4 c = p4[(BB * KK * HH / 4) + t];
    float4 bb = __ldg(&((const float4*)bu)[t & 31]);
    float4 o;
    o.x = fmaxf(a.x + c.x + bb.x, 0.f);
    o.y = fmaxf(a.y + c.y + bb.y, 0.f);
    o.z = fmaxf(a.z + c.z + bb.z, 0.f);
    o.w = fmaxf(a.w + c.w + bb.w, 0.f);
    ((float4*)out)[t] = o;
}

// ---------------------------------------------------------------------------
extern "C" void kernel_launch(void* const* d_in, const int* in_sizes, int n_in,
                              void* d_out, int out_size)
{
    const float* z  = (const float*)d_in[0];
    const int*   P  = (const int*)  d_in[1];
    const float* W1 = (const float*)d_in[2];
    const float* b1 = (const float*)d_in[3];
    const float* W2 = (const float*)d_in[4];
    const float* b2 = (const float*)d_in[5];
    const float* Wu = (const float*)d_in[6];
    const float* bu = (const float*)d_in[7];
    float* out = (float*)d_out;

    cudaFuncSetAttribute(kt1_gemm, cudaFuncAttributeMaxDynamicSharedMemorySize, SMEM_BYTES);
    cudaFuncSetAttribute(kt3_gemm, cudaFuncAttributeMaxDynamicSharedMemorySize, SMEM_BYTES);

    kt1_gemm<<<dim3(BB * KK / 32, 2), 128, SMEM_BYTES>>>(z, W1, b1, W2, b2);
    k2a_pairmax<<<256, 256>>>();
    k2_maxmsg<<<dim3(KK / 16, BB), 512>>>(P);
    kt3_gemm<<<dim3(BB * KK / 32, 2), 128, SMEM_BYTES>>>(z, Wu);
    k3_epi<<<BB * KK * HH / 4 / 256, 256>>>(bu, out);
}